// round 16
// baseline (speedup 1.0000x reference)
#include <cuda_runtime.h>
#include <cuda_fp16.h>
#include <cstdint>
#include <cstddef>

// ---------------------------------------------------------------------------
// FFB encoder (round 16 = round 15 + int8-plane sizing fix): main term f16
// mma.sync (xh@Whi) + corrections in int8 IMMA m16n8k32, power-of-2 scales:
//   corr*2^25 = (xl*2^16)@(W*2^9) + (x*2^5)@(Wlo*2^20)      [Ws plane]
//   corr*2^24 = (xl*2^16)@(W*2^8) + (x*2^5)@(Wlo*2^19)      [Wh plane]
// W streamed fragment-ordered from L2 (f16 hi + int8 parts); x int8 fragment
// arrays in smem, written by epilogue, read via LDS.128.
// Each int8 part = 65536 B/level; hi+lo = 131072 B/level (was the r15 bug).
// ---------------------------------------------------------------------------

#define TM    64
#define XH    264            // half stride of activation rows (528B: LDSM conflict-free)

// ---- SMEM byte offsets ----
#define SM_XSH  0            // 33792: xh f16 activations
#define SM_X8L  33792        // 16384: xl int8 A-fragments [4 mt][8 t8][32 lane][16B]
#define SM_X8H  50176        // 16384: x  int8 A-fragments
#define SM_GSM  66560        // 3072:  [6][64][2] f32 grid feats
#define SM_ASM  69632        // 12288: [6][2][256] f32
#define SM_W0M  81920        // 4096:  scaled W0/b0
#define SM_PSM  86016        // 768:   [64][3]
#define SMEM_TOTAL 86784

// f16 hi fragments: per level 65536 halves: [nb16][t16][lane][8 halves]
__device__ __align__(16) __half g_WsF[6 * 65536];
__device__ __align__(16) __half g_WhF[6 * 65536];
// int8 fragments: per level 131072 B = [part: hi|lo, 65536 B each]
//   part layout: [nb16: 16][t8: 8][lane: 32][16B]
__device__ __align__(16) int8_t g_Ws8[6 * 131072];
__device__ __align__(16) int8_t g_Wh8[6 * 131072];

__device__ __forceinline__ unsigned smem_u32(const void* p) {
    unsigned a;
    asm("{ .reg .u64 t; cvta.to.shared.u64 t, %1; cvt.u32.u64 %0, t; }" : "=r"(a) : "l"(p));
    return a;
}

__device__ __forceinline__ float sinr(float x) {
    float k = rintf(x * 0.15915494309189535f);
    float r = fmaf(k, -6.2831855f, x);
    r = fmaf(k, 1.7484555e-7f, r);
    return __sinf(r);
}

// A-fragment byte offset for int8 arrays: row r (0..63), k col (0..255)
__device__ __forceinline__ unsigned a8addr(int r, int k) {
    int mt = r >> 4, rr = r & 15;
    int lane = (rr & 7) * 4 + ((k & 15) >> 2);
    int reg = ((rr >> 3) & 1) + (((k >> 4) & 1) << 1);
    return (unsigned)((((mt * 8 + (k >> 5)) * 32 + lane) * 16) + reg * 4 + (k & 3));
}

// ---------------- prep: fragment-order W (f16 hi + int8 hi/lo) ----------------
__global__ void prep_kernel(const float* __restrict__ Ws, const float* __restrict__ Wh) {
    int idx = blockIdx.x * 256 + threadIdx.x;
    if (idx < 6 * 256 * 256) {
        int l = idx >> 16, rem = idx & 65535, n = rem >> 8, k = rem & 255;
        int src = (l << 16) + (k << 8) + n;
        float ws = 5.0f * Ws[src];
        float wh = 10.0f * Wh[src];
        __half wsh = __float2half_rn(ws), whh = __float2half_rn(wh);
        float wslo = ws - __half2float(wsh);
        float whlo = wh - __half2float(whh);
        int nb16 = n >> 4, g = n & 7, n8sub = (n >> 3) & 1;
        // f16 hi fragment (16-wide k steps)
        {
            int t = k >> 4, kk = k & 15;
            int khi = kk >> 3, tg2 = (kk & 7) >> 1, kp = kk & 1;
            size_t dF = (size_t)l * 65536 + (size_t)(nb16 * 16 + t) * 256
                      + (g * 4 + tg2) * 8 + (n8sub * 4 + khi * 2 + kp);
            g_WsF[dF] = wsh;
            g_WhF[dF] = whh;
        }
        // int8 fragments (32-wide k steps); hi part [0,65536), lo at +65536
        {
            int t8 = k >> 5;
            int lane8 = g * 4 + ((k & 15) >> 2);
            int byteslot = n8sub * 8 + ((k >> 4) & 1) * 4 + (k & 3);
            size_t d8 = (size_t)l * 131072 + (size_t)((nb16 * 8 + t8) * 32 + lane8) * 16 + byteslot;
            g_Ws8[d8]         = (int8_t)__float2int_rn(ws   * 512.0f);      // 2^9
            g_Ws8[d8 + 65536] = (int8_t)__float2int_rn(wslo * 1048576.0f);  // 2^20
            g_Wh8[d8]         = (int8_t)__float2int_rn(wh   * 256.0f);      // 2^8
            g_Wh8[d8 + 65536] = (int8_t)__float2int_rn(whlo * 524288.0f);   // 2^19
        }
    }
}

__device__ __forceinline__ void mma16816(float* c, const unsigned* a, unsigned b0, unsigned b1) {
    asm volatile(
        "mma.sync.aligned.m16n8k16.row.col.f32.f16.f16.f32 "
        "{%0,%1,%2,%3}, {%4,%5,%6,%7}, {%8,%9}, {%0,%1,%2,%3};\n"
        : "+f"(c[0]), "+f"(c[1]), "+f"(c[2]), "+f"(c[3])
        : "r"(a[0]), "r"(a[1]), "r"(a[2]), "r"(a[3]), "r"(b0), "r"(b1));
}

__device__ __forceinline__ void imma16832(int* c, uint4 a, unsigned b0, unsigned b1) {
    asm volatile(
        "mma.sync.aligned.m16n8k32.row.col.s32.s8.s8.s32 "
        "{%0,%1,%2,%3}, {%4,%5,%6,%7}, {%8,%9}, {%0,%1,%2,%3};\n"
        : "+r"(c[0]), "+r"(c[1]), "+r"(c[2]), "+r"(c[3])
        : "r"(a.x), "r"(a.y), "r"(a.z), "r"(a.w), "r"(b0), "r"(b1));
}

#define LDSM_X4(r0, r1, r2, r3, addr) \
    asm volatile("ldmatrix.sync.aligned.m8n8.x4.shared.b16 {%0,%1,%2,%3}, [%4];" \
        : "=r"(r0), "=r"(r1), "=r"(r2), "=r"(r3) : "r"(addr))

#define LDS128(v, addr) \
    asm volatile("ld.shared.v4.u32 {%0,%1,%2,%3}, [%4];" \
        : "=r"((v).x), "=r"((v).y), "=r"((v).z), "=r"((v).w) : "r"(addr))

// one int8 correction pass: cs += A8(smem)@B8(gmem), 8 k32-steps, dbl-buffered B
__device__ __forceinline__ void corr_pass(int (&cs)[2][4][4], const uint4* __restrict__ p8,
                                          unsigned abase) {
    uint4 b0c = p8[0], b1c = p8[256];
    #pragma unroll
    for (int tp = 0; tp < 8; tp++) {
        uint4 b0n, b1n;
        if (tp < 7) {
            b0n = p8[(tp + 1) * 32];
            b1n = p8[256 + (tp + 1) * 32];
        }
        uint4 a0, a1;
        unsigned sa = abase + (unsigned)(tp * 512);
        LDS128(a0, sa);
        LDS128(a1, sa + 4096);
        imma16832(cs[0][0], a0, b0c.x, b0c.y);
        imma16832(cs[0][1], a0, b0c.z, b0c.w);
        imma16832(cs[0][2], a0, b1c.x, b1c.y);
        imma16832(cs[0][3], a0, b1c.z, b1c.w);
        imma16832(cs[1][0], a1, b0c.x, b0c.y);
        imma16832(cs[1][1], a1, b0c.z, b0c.w);
        imma16832(cs[1][2], a1, b1c.x, b1c.y);
        imma16832(cs[1][3], a1, b1c.z, b1c.w);
        b0c = b0n; b1c = b1n;
    }
}

// C[64,256] = corr(int8)*sinv + bias + xh @ Whi^T (f16). 16 warps 2m x 8n.
__device__ __forceinline__ void do_gemm(float (&c)[2][4][4],
        const __half* __restrict__ wfH, const int8_t* __restrict__ wf8,
        float sinv, const float2 (&bv)[4],
        unsigned sbase, unsigned aoff0, unsigned aoff1, unsigned boffH,
        unsigned a8off, unsigned b8u4) {
    // ---------- correction: int8 IMMA ----------
    int cs[2][4][4];
    #pragma unroll
    for (int mt = 0; mt < 2; mt++)
        #pragma unroll
        for (int nt = 0; nt < 4; nt++)
            #pragma unroll
            for (int e = 0; e < 4; e++) cs[mt][nt][e] = 0;
    const uint4* p8 = (const uint4*)wf8 + b8u4;
    corr_pass(cs, p8, sbase + SM_X8L + a8off);           // xl @ W8
    corr_pass(cs, p8 + 4096, sbase + SM_X8H + a8off);    // x  @ Wlo8  (lo part +65536 B)
    #pragma unroll
    for (int mt = 0; mt < 2; mt++)
        #pragma unroll
        for (int nt = 0; nt < 4; nt++) {
            c[mt][nt][0] = fmaf((float)cs[mt][nt][0], sinv, bv[nt].x);
            c[mt][nt][1] = fmaf((float)cs[mt][nt][1], sinv, bv[nt].y);
            c[mt][nt][2] = fmaf((float)cs[mt][nt][2], sinv, bv[nt].x);
            c[mt][nt][3] = fmaf((float)cs[mt][nt][3], sinv, bv[nt].y);
        }
    // ---------- main term: f16 ----------
    const uint4* __restrict__ ph = (const uint4*)(wfH + boffH);
    uint4 vh[2][2];
    vh[0][0] = ph[0]; vh[0][1] = ph[512];
    #pragma unroll 2
    for (int t = 0; t < 16; t++) {
        const int cur = t & 1, nxt = cur ^ 1;
        if (t < 15) {
            vh[nxt][0] = ph[(t + 1) * 32];
            vh[nxt][1] = ph[512 + (t + 1) * 32];
        }
        unsigned koff = (unsigned)(t * 32);
        unsigned ah0[4], ah1[4];
        LDSM_X4(ah0[0], ah0[1], ah0[2], ah0[3], sbase + SM_XSH + aoff0 + koff);
        LDSM_X4(ah1[0], ah1[1], ah1[2], ah1[3], sbase + SM_XSH + aoff1 + koff);
        mma16816(c[0][0], ah0, vh[cur][0].x, vh[cur][0].y);
        mma16816(c[0][1], ah0, vh[cur][0].z, vh[cur][0].w);
        mma16816(c[0][2], ah0, vh[cur][1].x, vh[cur][1].y);
        mma16816(c[0][3], ah0, vh[cur][1].z, vh[cur][1].w);
        mma16816(c[1][0], ah1, vh[cur][0].x, vh[cur][0].y);
        mma16816(c[1][1], ah1, vh[cur][0].z, vh[cur][0].w);
        mma16816(c[1][2], ah1, vh[cur][1].x, vh[cur][1].y);
        mma16816(c[1][3], ah1, vh[cur][1].z, vh[cur][1].w);
    }
}

__global__ void __launch_bounds__(512, 1) ffb_kernel(
    const float* __restrict__ in_pos, const float* __restrict__ table,
    const float* __restrict__ ffn_A, const float* __restrict__ W0,
    const float* __restrict__ b0v, const float* __restrict__ bsv,
    const float* __restrict__ bhv, float* __restrict__ out) {
    extern __shared__ char smem[];
    const unsigned sbase = smem_u32(smem);
    __half* xsh = (__half*)(smem + SM_XSH);
    float* gsm = (float*)(smem + SM_GSM);
    float* Asm = (float*)(smem + SM_ASM);
    float* w0m = (float*)(smem + SM_W0M);
    float* psm = (float*)(smem + SM_PSM);

    const int tid = threadIdx.x;
    const int lane = tid & 31, wid = tid >> 5;
    const int g = lane >> 2, tg = lane & 3;
    const int wm = wid >> 3, wn = wid & 7;        // 2m x 8n warps
    const int rm = wm * 32, cn = wn * 32;
    const int row0 = blockIdx.x * TM;

    const unsigned aoff0 = (unsigned)((rm + (lane & 15)) * XH + ((lane >> 4) << 3)) * 2;
    const unsigned aoff1 = aoff0 + (unsigned)(16 * XH) * 2;
    const unsigned boffH = (unsigned)(wn * 8192 + lane * 8);
    const unsigned a8off = (unsigned)(wm * 8192 + lane * 16);
    const unsigned b8u4  = (unsigned)(wn * 512 + lane);

    // ---- prologue staging ----
    for (int i = tid; i < TM * 3; i += 512) psm[i] = in_pos[row0 * 3 + i];
    for (int i = tid; i < 6 * 512; i += 512) {
        int l = i >> 9;
        Asm[i] = 6.283185307179586f * (5.0f * (float)(1 << l)) * ffn_A[i];
    }
    if (tid < 256) {
        w0m[tid] = 5.0f * W0[tid];
        w0m[256 + tid] = 5.0f * W0[256 + tid];
        w0m[512 + tid] = 5.0f * W0[512 + tid];
        w0m[768 + tid] = 5.0f * b0v[tid];
    }
    __syncthreads();

    // ---- multires hash grid (f32 math matches reference) ----
    if (tid < TM * 6) {
        int t = tid;
        int l = t >> 6;
        int p = t & 63;
        float res = 16.0f * (float)(1 << l);
        float px = (psm[p * 3 + 0] + 1.0f) * 0.5f * res;
        float py = (psm[p * 3 + 1] + 1.0f) * 0.5f * res;
        float pz = (psm[p * 3 + 2] + 1.0f) * 0.5f * res;
        float fx = floorf(px), fy = floorf(py), fz = floorf(pz);
        float frx = px - fx, fry = py - fy, frz = pz - fz;
        int ix = (int)fx, iy = (int)fy, iz = (int)fz;
        float g0 = 0.f, g1 = 0.f;
        const float* tb = table + (size_t)l * (524288 * 2);
        #pragma unroll
        for (int cc = 0; cc < 8; cc++) {
            int ox = (cc >> 2) & 1, oy = (cc >> 1) & 1, oz = cc & 1;
            unsigned h = ((unsigned)(ix + ox))
                       ^ ((unsigned)(iy + oy) * 2654435761u)
                       ^ ((unsigned)(iz + oz) * 805459861u);
            h &= 524287u;
            float2 f2 = *(const float2*)(tb + (size_t)h * 2);
            float w = (ox ? frx : 1.0f - frx) * (oy ? fry : 1.0f - fry) * (oz ? frz : 1.0f - frz);
            g0 = fmaf(w, f2.x, g0);
            g1 = fmaf(w, f2.y, g1);
        }
        gsm[t * 2] = g0; gsm[t * 2 + 1] = g1;
    }

    // ---- layer 0: x = sin(5*(pos @ W0 + b0)) -> xh f16 + int8 fragments ----
    for (int i = tid; i < TM * 128; i += 512) {
        int p = i >> 7, n0 = (i & 127) * 2;
        float pxx = psm[p * 3], pyy = psm[p * 3 + 1], pzz = psm[p * 3 + 2];
        float x0 = sinr(fmaf(pzz, w0m[512 + n0], fmaf(pyy, w0m[256 + n0], fmaf(pxx, w0m[n0], w0m[768 + n0]))));
        float x1 = sinr(fmaf(pzz, w0m[513 + n0], fmaf(pyy, w0m[257 + n0], fmaf(pxx, w0m[n0 + 1], w0m[769 + n0]))));
        __half h0 = __float2half_rn(x0), h1 = __float2half_rn(x1);
        *(__half2*)(xsh + p * XH + n0) = __halves2half2(h0, h1);
        int l0 = __float2int_rn((x0 - __half2float(h0)) * 65536.f);
        int l1 = __float2int_rn((x1 - __half2float(h1)) * 65536.f);
        int q0 = __float2int_rn(x0 * 32.f);
        int q1 = __float2int_rn(x1 * 32.f);
        unsigned off = a8addr(p, n0);
        *(unsigned short*)(smem + SM_X8L + off) = (unsigned short)((l0 & 0xFF) | ((l1 & 0xFF) << 8));
        *(unsigned short*)(smem + SM_X8H + off) = (unsigned short)((q0 & 0xFF) | ((q1 & 0xFF) << 8));
    }
    __syncthreads();

    float acc[2][4][4];
    #pragma unroll
    for (int mt = 0; mt < 2; mt++)
        #pragma unroll
        for (int nt = 0; nt < 4; nt++)
            #pragma unroll
            for (int e = 0; e < 4; e++) acc[mt][nt][e] = 0.f;

    const float SINV1 = 1.0f / 33554432.0f;   // 2^-25 (Ws plane)
    const float SINV2 = 1.0f / 16777216.0f;   // 2^-24 (Wh plane)

    for (int lev = 0; lev < 6; lev++) {
        // ---- GEMM1: c = xs @ (5*Ws)^T + 5*bs ----
        float2 bv[4];
        #pragma unroll
        for (int nt = 0; nt < 4; nt++) {
            float2 b = *(const float2*)(bsv + lev * 256 + cn + nt * 8 + 2 * tg);
            bv[nt] = make_float2(5.0f * b.x, 5.0f * b.y);
        }
        float c[2][4][4];
        do_gemm(c, g_WsF + (size_t)lev * 65536, g_Ws8 + (size_t)lev * 131072,
                SINV1, bv, sbase, aoff0, aoff1, boffH, a8off, b8u4);
        __syncthreads();   // all reads of xs/frags done: WAR safe

        // ---- epilogue 1: x = sin(c) + sin(grid proj); write xh + int8 frags ----
        #pragma unroll
        for (int mt = 0; mt < 2; mt++) {
            int r0 = rm + mt * 16 + g;
            float2 gA = *(const float2*)(gsm + (lev * 64 + r0) * 2);
            float2 gB = *(const float2*)(gsm + (lev * 64 + r0 + 8) * 2);
            #pragma unroll
            for (int nt = 0; nt < 4; nt++) {
                int n0 = cn + nt * 8 + 2 * tg;
                float2 a0 = *(const float2*)(Asm + lev * 512 + n0);
                float2 a1 = *(const float2*)(Asm + lev * 512 + 256 + n0);
                float x0 = sinr(c[mt][nt][0]) + sinr(fmaf(gA.y, a1.x, gA.x * a0.x));
                float x1 = sinr(c[mt][nt][1]) + sinr(fmaf(gA.y, a1.y, gA.x * a0.y));
                float x2 = sinr(c[mt][nt][2]) + sinr(fmaf(gB.y, a1.x, gB.x * a0.x));
                float x3 = sinr(c[mt][nt][3]) + sinr(fmaf(gB.y, a1.y, gB.x * a0.y));
                __half h0 = __float2half_rn(x0), h1 = __float2half_rn(x1);
                __half h2 = __float2half_rn(x2), h3 = __float2half_rn(x3);
                *(__half2*)(xsh + r0 * XH + n0)       = __halves2half2(h0, h1);
                *(__half2*)(xsh + (r0 + 8) * XH + n0) = __halves2half2(h2, h3);
                int l0 = __float2int_rn((x0 - __half2float(h0)) * 65536.f);
                int l1 = __float2int_rn((x1 - __half2float(h1)) * 65536.f);
                int l2 = __float2int_rn((x2 - __half2float(h2)) * 65536.f);
                int l3 = __float2int_rn((x3 - __half2float(h3)) * 65536.f);
                int q0 = __float2int_rn(x0 * 32.f), q1 = __float2int_rn(x1 * 32.f);
                int q2 = __float2int_rn(x2 * 32.f), q3 = __float2int_rn(x3 * 32.f);
                unsigned oA = a8addr(r0, n0);
                unsigned oB = a8addr(r0 + 8, n0);
                *(unsigned short*)(smem + SM_X8L + oA) = (unsigned short)((l0 & 0xFF) | ((l1 & 0xFF) << 8));
                *(unsigned short*)(smem + SM_X8L + oB) = (unsigned short)((l2 & 0xFF) | ((l3 & 0xFF) << 8));
                *(unsigned short*)(smem + SM_X8H + oA) = (unsigned short)((q0 & 0xFF) | ((q1 & 0xFF) << 8));
                *(unsigned short*)(smem + SM_X8H + oB) = (unsigned short)((q2 & 0xFF) | ((q3 & 0xFF) << 8));
            }
        }
        __syncthreads();   // xs/frag writes visible before GEMM2 reads

        // ---- GEMM2: c2 = xs @ (10*Wh)^T + 10*bh; out += sin(c2) ----
        float2 bv2[4];
        #pragma unroll
        for (int nt = 0; nt < 4; nt++) {
            float2 b = *(const float2*)(bhv + lev * 256 + cn + nt * 8 + 2 * tg);
            bv2[nt] = make_float2(10.0f * b.x, 10.0f * b.y);
        }
        float c2[2][4][4];
        do_gemm(c2, g_WhF + (size_t)lev * 65536, g_Wh8 + (size_t)lev * 131072,
                SINV2, bv2, sbase, aoff0, aoff1, boffH, a8off, b8u4);

        // ---- epilogue 2: register-only accumulate ----
        #pragma unroll
        for (int mt = 0; mt < 2; mt++)
            #pragma unroll
            for (int nt = 0; nt < 4; nt++)
                #pragma unroll
                for (int e = 0; e < 4; e++)
                    acc[mt][nt][e] += sinr(c2[mt][nt][e]);
        // no barrier: next GEMM1 re-reads the SAME xs/frag arrays
    }

    // ---- store out [N,256] f32 ----
    #pragma unroll
    for (int mt = 0; mt < 2; mt++)
        #pragma unroll
        for (int nt = 0; nt < 4; nt++) {
            int r = row0 + rm + mt * 16 + g;
            int n0 = cn + nt * 8 + 2 * tg;
            *(float2*)(out + (size_t)r * 256 + n0) = make_float2(acc[mt][nt][0], acc[mt][nt][1]);
            *(float2*)(out + (size_t)(r + 8) * 256 + n0) = make_float2(acc[mt][nt][2], acc[mt][nt][3]);
        }
}

extern "C" void kernel_launch(void* const* d_in, const int* in_sizes, int n_in,
                              void* d_out, int out_size) {
    (void)in_sizes; (void)n_in; (void)out_size;
    const float* in_pos = (const float*)d_in[0];
    const float* table  = (const float*)d_in[1];
    const float* ffn_A  = (const float*)d_in[2];
    const float* W0     = (const float*)d_in[3];
    const float* b0     = (const float*)d_in[4];
    const float* Ws     = (const float*)d_in[5];
    const float* bs     = (const float*)d_in[6];
    const float* Wh     = (const float*)d_in[7];
    const float* bh     = (const float*)d_in[8];
    float* out = (float*)d_out;

    cudaFuncSetAttribute(ffb_kernel, cudaFuncAttributeMaxDynamicSharedMemorySize, SMEM_TOTAL);

    prep_kernel<<<1536, 256>>>(Ws, Wh);
    ffb_kernel<<<262144 / TM, 512, SMEM_TOTAL>>>(in_pos, table, ffn_A, W0, b0, bs, bh, out);
}